// round 10
// baseline (speedup 1.0000x reference)
#include <cuda_runtime.h>
#include <cuda_bf16.h>
#include <cstdint>

#define B_TOK 8192
#define D_IN  1024
#define D_OUT 1024
#define NE    16
#define TOPK  2
#define NH    64
#define TILE_M 128

// ---------------- device scratch (static allocations only) ----------------
__device__ int   g_cnt[NE];
__device__ int   g_dst[NE * B_TOK];
__device__ float g_gw[NE * B_TOK];

// bf16 hi/lo split weights (same layout as source, no transpose)
__device__ __nv_bfloat16 g_W1s_hi[NE * D_IN * NH];    // [e][k][h]
__device__ __nv_bfloat16 g_W1s_lo[NE * D_IN * NH];
__device__ __nv_bfloat16 g_W2s_hi[NE * NH * D_OUT];   // [e][h][o]
__device__ __nv_bfloat16 g_W2s_lo[NE * NH * D_OUT];

// ---------------- helpers ----------------
__device__ __forceinline__ uint32_t smem_u32(const void* p) {
    uint32_t a;
    asm("{ .reg .u64 t; cvta.to.shared.u64 t, %1; cvt.u32.u64 %0, t; }" : "=r"(a) : "l"(p));
    return a;
}
__device__ __forceinline__ void cp16s(uint32_t sa, const void* g) {
    asm volatile("cp.async.cg.shared.global [%0], [%1], 16;\n" :: "r"(sa), "l"(g));
}
__device__ __forceinline__ void cp_commit() { asm volatile("cp.async.commit_group;\n"); }
template<int N> __device__ __forceinline__ void cp_wait() {
    asm volatile("cp.async.wait_group %0;\n" :: "n"(N));
}
__device__ __forceinline__ void sts128(uint32_t a, uint32_t r0, uint32_t r1,
                                       uint32_t r2, uint32_t r3) {
    asm volatile("st.shared.v4.b32 [%0], {%1,%2,%3,%4};"
                 :: "r"(a), "r"(r0), "r"(r1), "r"(r2), "r"(r3) : "memory");
}
__device__ __forceinline__ void ldsm4(uint32_t a, uint32_t* r) {
    asm volatile("ldmatrix.sync.aligned.m8n8.x4.shared.b16 {%0,%1,%2,%3}, [%4];"
                 : "=r"(r[0]), "=r"(r[1]), "=r"(r[2]), "=r"(r[3]) : "r"(a));
}
__device__ __forceinline__ void ldsm4t(uint32_t a, uint32_t* r) {
    asm volatile("ldmatrix.sync.aligned.m8n8.x4.trans.shared.b16 {%0,%1,%2,%3}, [%4];"
                 : "=r"(r[0]), "=r"(r[1]), "=r"(r[2]), "=r"(r[3]) : "r"(a));
}
__device__ __forceinline__ void mma16816(float* d, const uint32_t* a, const uint32_t* b) {
    asm volatile("mma.sync.aligned.m16n8k16.row.col.f32.bf16.bf16.f32 "
                 "{%0,%1,%2,%3}, {%4,%5,%6,%7}, {%8,%9}, {%0,%1,%2,%3};"
                 : "+f"(d[0]), "+f"(d[1]), "+f"(d[2]), "+f"(d[3])
                 : "r"(a[0]), "r"(a[1]), "r"(a[2]), "r"(a[3]), "r"(b[0]), "r"(b[1]));
}
__device__ __forceinline__ void red2(float* gaddr, float v0, float v1) {
    asm volatile("red.global.add.v2.f32 [%0], {%1, %2};"
                 :: "l"(gaddr), "f"(v0), "f"(v1) : "memory");
}

// pack (lo half = f0, hi half = f1) into bf16x2
__device__ __forceinline__ uint32_t pk_bf(float f0, float f1) {
    uint32_t r;
    asm("cvt.rn.bf16x2.f32 %0, %1, %2;" : "=r"(r) : "f"(f1), "f"(f0));
    return r;
}
__device__ __forceinline__ float bf_lo_f(uint32_t p) { return __uint_as_float(p << 16); }
__device__ __forceinline__ float bf_hi_f(uint32_t p) { return __uint_as_float(p & 0xFFFF0000u); }

__device__ __forceinline__ void top2_insert(float v, int e, float& v0, int& i0,
                                            float& v1, int& i1) {
    if (v > v0 || (v == v0 && e < i0)) { v1 = v0; i1 = i0; v0 = v; i0 = e; }
    else if (v > v1 || (v == v1 && e < i1)) { v1 = v; i1 = e; }
}

// ---------------- kernel 0: reset counters ----------------
__global__ void reset_kernel() {
    if (threadIdx.x < NE) g_cnt[threadIdx.x] = 0;
}

// ---------------- kernel: zero output (out is poisoned each replay) ----------------
__global__ void __launch_bounds__(256) zero_out_kernel(float4* __restrict__ out) {
    out[blockIdx.x * 256 + threadIdx.x] = make_float4(0.f, 0.f, 0.f, 0.f);
}

// ---------------- kernel: hi/lo split (no transpose) ----------------
__global__ void __launch_bounds__(256) split_kernel(
    const float* __restrict__ src, __nv_bfloat16* __restrict__ hi,
    __nv_bfloat16* __restrict__ lo, int n)
{
    int i = blockIdx.x * 256 + threadIdx.x;
    if (i < n) {
        float v = src[i];
        __nv_bfloat16 h = __float2bfloat16_rn(v);
        hi[i] = h;
        lo[i] = __float2bfloat16_rn(v - __bfloat162float(h));
    }
}

// ---------------- kernel 1: gating + top-2 + append ----------------
// block = 128 threads = 32 tokens x 4 expert-quads; grid = 256
// 4-stage cp.async pipeline (3 chunks in flight). Per-expert summation order is
// bitwise-identical to the validated gate (chunk-local accumulators, sequential kk).
#define GT 32
__global__ void __launch_bounds__(128) gate_kernel(
    const float* __restrict__ x, const float* __restrict__ Wg,
    const float* __restrict__ bg)
{
    __shared__ float Xs[4][GT][68];    // padded rows (272B, 16B granular)
    __shared__ float Wgs[4][64][16];
    const int tid = threadIdx.x;
    const int tl  = tid >> 2;          // token-in-block 0..31
    const int eb  = tid & 3;           // expert quad 0..3
    const int t0  = blockIdx.x * GT;

    const uint32_t xs_b  = smem_u32(&Xs[0][0][0]);
    const uint32_t wgs_b = smem_u32(&Wgs[0][0][0]);

    auto loadX = [&](int c, int b) {
        #pragma unroll
        for (int i = 0; i < 4; i++) {
            int f = tid + i * 128;          // 512 float4 tasks
            int r = f >> 4, c4 = f & 15;
            cp16s(xs_b + (uint32_t)(b * GT * 68 + r * 68 + c4 * 4) * 4,
                  &x[(t0 + r) * D_IN + c * 64 + c4 * 4]);
        }
    };
    auto loadW = [&](int c, int b) {
        #pragma unroll
        for (int i = 0; i < 2; i++) {
            int f = tid + i * 128;          // 256 float4 tasks
            int r = f >> 2, c4 = f & 3;
            cp16s(wgs_b + (uint32_t)(b * 64 * 16 + r * 16 + c4 * 4) * 4,
                  &Wg[(c * 64 + r) * NE + c4 * 4]);
        }
    };

    float tot0 = 0.f, tot1 = 0.f, tot2 = 0.f, tot3 = 0.f;

    #pragma unroll
    for (int s = 0; s < 3; s++) { loadX(s, s); loadW(s, s); cp_commit(); }

    #pragma unroll 1
    for (int c = 0; c < 16; c++) {
        const int b = c & 3;
        cp_wait<2>(); __syncthreads();
        if (c + 3 < 16) { loadX(c + 3, (c + 3) & 3); loadW(c + 3, (c + 3) & 3); }
        cp_commit();
        // chunk-local accumulators (identical order to validated gate)
        float a0 = 0.f, a1 = 0.f, a2 = 0.f, a3 = 0.f;
        #pragma unroll 16
        for (int kk = 0; kk < 64; kk++) {
            float xv = Xs[b][tl][kk];
            float4 w = *(const float4*)&Wgs[b][kk][eb * 4];
            a0 += xv * w.x; a1 += xv * w.y; a2 += xv * w.z; a3 += xv * w.w;
        }
        tot0 += a0; tot1 += a1; tot2 += a2; tot3 += a3;
    }

    float4 bgv = *(const float4*)&bg[eb * 4];
    tot0 += bgv.x; tot1 += bgv.y; tot2 += bgv.z; tot3 += bgv.w;

    // local top-2 among my 4 experts (jax tie-break: lower index wins)
    float v0 = -3.402823466e38f, v1 = -3.402823466e38f;
    int   i0 = NE, i1 = NE;
    top2_insert(tot0, eb * 4 + 0, v0, i0, v1, i1);
    top2_insert(tot1, eb * 4 + 1, v0, i0, v1, i1);
    top2_insert(tot2, eb * 4 + 2, v0, i0, v1, i1);
    top2_insert(tot3, eb * 4 + 3, v0, i0, v1, i1);

    const unsigned m = 0xFFFFFFFFu;
    #pragma unroll
    for (int d = 1; d < 4; d <<= 1) {
        float ov0 = __shfl_xor_sync(m, v0, d);
        int   oi0 = __shfl_xor_sync(m, i0, d);
        float ov1 = __shfl_xor_sync(m, v1, d);
        int   oi1 = __shfl_xor_sync(m, i1, d);
        top2_insert(ov0, oi0, v0, i0, v1, i1);
        top2_insert(ov1, oi1, v0, i0, v1, i1);
    }

    if (eb == 0) {
        int tok = t0 + tl;
        float r   = expf(v1 - v0);
        float inv = 1.0f / (1.0f + r);
        int p0 = atomicAdd(&g_cnt[i0], 1);
        g_dst[i0 * B_TOK + p0] = tok * 2;
        g_gw [i0 * B_TOK + p0] = inv;
        int p1 = atomicAdd(&g_cnt[i1], 1);
        g_dst[i1 * B_TOK + p1] = tok * 2 + 1;
        g_gw [i1 * B_TOK + p1] = r * inv;
    }
}

// ---------------- kernel 2: HMMA grouped expert MLP ----------------
// dyn smem (from 1024-aligned base SB), all byte offsets:
//   Hhi @ 0 (18432 = 128 rows * 144B)   Hlo @ 18432          (36864 total)
//   pool @ 36864:
//     Phase A buf b @ pool + b*55296:
//       Xhi(18432: 128r x 144B) Xlo(+18432) W1hi(+36864, 64r x 144B = 9216) W1lo(+46080)
//     Phase B buf b @ pool + b*34816:
//       W2hi(17408: 64r x 272B) W2lo(+17408)
#define SM_POOL 36864
#define SM_DYN  (36864 + 2*55296 + 1024)

__global__ void __launch_bounds__(256, 1) expert_kernel(
    const float* __restrict__ x, const float* __restrict__ b1,
    const float* __restrict__ b2, float* __restrict__ out)
{
    const int e    = blockIdx.y;
    const int n    = g_cnt[e];
    const int base = blockIdx.x * TILE_M;
    if (base >= n) return;

    const int tid = threadIdx.x;
    const int wid = tid >> 5, lid = tid & 31;
    const int wm  = wid & 3, wn = wid >> 2;     // warp grid 4(M) x 2(N)

    __shared__ int   s_dst[TILE_M];
    __shared__ int   s_tok[TILE_M];
    __shared__ float s_w[TILE_M];
    extern __shared__ char dynsm[];
    const uint32_t SB = (smem_u32(dynsm) + 1023u) & ~1023u;
    const uint32_t SP = SB + SM_POOL;

    if (tid < TILE_M) {
        int slot = base + tid;
        if (slot < n) {
            int d = g_dst[e * B_TOK + slot];
            s_dst[tid] = d; s_tok[tid] = d >> 1;
            s_w[tid] = g_gw[e * B_TOK + slot];
        } else { s_dst[tid] = -1; s_tok[tid] = 0; s_w[tid] = 0.f; }
    }
    __syncthreads();

    // ================= Phase A: H = relu(X @ W1 + b1) =================
    const int arow = tid >> 1, ahalf = tid & 1;
    const float* xrow = x + (size_t)s_tok[arow] * D_IN + ahalf * 32;
    float4 xr[8];

    auto ldgX = [&](int c) {
        const float* p = xrow + c * 64;
        #pragma unroll
        for (int j = 0; j < 8; j++) xr[j] = *(const float4*)(p + j * 4);
    };
    auto stsX = [&](int b) {
        uint32_t hib = SP + b * 55296;
        uint32_t lob = hib + 18432;
        uint32_t hi[16], lo[16];
        #pragma unroll
        for (int j = 0; j < 8; j++) {
            float f0 = xr[j].x, f1 = xr[j].y, f2 = xr[j].z, f3 = xr[j].w;
            uint32_t h0 = pk_bf(f0, f1), h1 = pk_bf(f2, f3);
            hi[2*j] = h0; hi[2*j+1] = h1;
            lo[2*j]   = pk_bf(f0 - bf_lo_f(h0), f1 - bf_hi_f(h0));
            lo[2*j+1] = pk_bf(f2 - bf_lo_f(h1), f3 - bf_hi_f(h1));
        }
        uint32_t rb = arow * 144 + ahalf * 64;
        #pragma unroll
        for (int q = 0; q < 4; q++) {
            sts128(hib + rb + q * 16, hi[4*q], hi[4*q+1], hi[4*q+2], hi[4*q+3]);
            sts128(lob + rb + q * 16, lo[4*q], lo[4*q+1], lo[4*q+2], lo[4*q+3]);
        }
    };
    auto cpW1 = [&](int c, int b) {
        uint32_t hib = SP + b * 55296 + 36864;
        uint32_t lob = hib + 9216;
        #pragma unroll
        for (int i = 0; i < 2; i++) {
            int f = tid + i * 256;               // 0..511
            int r = f >> 3, s = f & 7;
            uint32_t off = r * 144 + s * 16;
            int gi = (e * D_IN + c * 64 + r) * NH + s * 8;
            cp16s(hib + off, &g_W1s_hi[gi]);
            cp16s(lob + off, &g_W1s_lo[gi]);
        }
    };

    float accA[2][4][4];
    #pragma unroll
    for (int mb = 0; mb < 2; mb++)
        #pragma unroll
        for (int nb = 0; nb < 4; nb++)
            #pragma unroll
            for (int q = 0; q < 4; q++) accA[mb][nb][q] = 0.f;

    auto computeA = [&](int b) {
        uint32_t Xb = SP + b * 55296;
        uint32_t Wb = Xb + 36864;
        #pragma unroll
        for (int ks = 0; ks < 4; ks++) {
            uint32_t ah[2][4], al[2][4];
            #pragma unroll
            for (int mb = 0; mb < 2; mb++) {
                uint32_t ad = Xb + (wm*32 + mb*16 + (lid & 15)) * 144
                            + ks * 32 + ((lid >> 4) << 4);
                ldsm4(ad, ah[mb]);
                ldsm4(ad + 18432, al[mb]);
            }
            #pragma unroll
            for (int j = 0; j < 2; j++) {
                uint32_t bd = Wb + (ks*16 + (lid & 15)) * 144
                            + (wn*32 + j*16 + ((lid >> 4) << 3)) * 2;
                uint32_t bh[4], bl[4];
                ldsm4t(bd, bh);
                ldsm4t(bd + 9216, bl);
                #pragma unroll
                for (int mb = 0; mb < 2; mb++)
                    #pragma unroll
                    for (int nn = 0; nn < 2; nn++) {
                        int nb = j*2 + nn;
                        mma16816(accA[mb][nb], ah[mb], bh + nn*2);
                        mma16816(accA[mb][nb], ah[mb], bl + nn*2);
                        mma16816(accA[mb][nb], al[mb], bh + nn*2);
                    }
            }
        }
    };

    ldgX(0);
    stsX(0);
    cpW1(0, 0); cp_commit();
    ldgX(1);
    cp_wait<0>(); __syncthreads();
    #pragma unroll 1
    for (int c = 0; c < 16; c++) {
        const int b = c & 1;
        if (c < 15) {
            stsX(b ^ 1);                      // xr holds chunk c+1
            cpW1(c + 1, b ^ 1); cp_commit();
            if (c < 14) ldgX(c + 2);
        }
        computeA(b);
        if (c < 15) { cp_wait<0>(); __syncthreads(); }
    }

    // ---- epilogue A: bias + relu -> bf16 hi/lo H tiles ----
    {
        char* SBp = dynsm + (SB - smem_u32(dynsm));
        #pragma unroll
        for (int mb = 0; mb < 2; mb++) {
            int r = wm*32 + mb*16 + (lid >> 2);
            #pragma unroll
            for (int nb = 0; nb < 4; nb++) {
                int col = wn*32 + nb*8 + (lid & 3) * 2;
                float bb0 = b1[e * NH + col], bb1 = b1[e * NH + col + 1];
                float v0 = fmaxf(accA[mb][nb][0] + bb0, 0.f);
                float v1 = fmaxf(accA[mb][nb][1] + bb1, 0.f);
                uint32_t h = pk_bf(v0, v1);
                uint32_t l = pk_bf(v0 - bf_lo_f(h), v1 - bf_hi_f(h));
                *(uint32_t*)(SBp + r * 144 + col * 2)         = h;
                *(uint32_t*)(SBp + 18432 + r * 144 + col * 2) = l;
                v0 = fmaxf(accA[mb][nb][2] + bb0, 0.f);
                v1 = fmaxf(accA[mb][nb][3] + bb1, 0.f);
                h = pk_bf(v0, v1);
                l = pk_bf(v0 - bf_lo_f(h), v1 - bf_hi_f(h));
                *(uint32_t*)(SBp + (r + 8) * 144 + col * 2)         = h;
                *(uint32_t*)(SBp + 18432 + (r + 8) * 144 + col * 2) = l;
            }
        }
    }
    __syncthreads();

    // ================= Phase B: Y = w * (H @ W2 + b2) -> red.add to out =================
    auto cpW2 = [&](int cn, int b) {
        uint32_t hib = SP + b * 34816;
        uint32_t lob = hib + 17408;
        #pragma unroll
        for (int i = 0; i < 4; i++) {
            int f = tid + i * 256;               // 0..1023
            int r = f >> 4, s = f & 15;
            uint32_t off = r * 272 + s * 16;
            int gi = (e * NH + r) * D_OUT + cn * 128 + s * 8;
            cp16s(hib + off, &g_W2s_hi[gi]);
            cp16s(lob + off, &g_W2s_lo[gi]);
        }
    };

    cpW2(0, 0); cp_commit();
    cp_wait<0>(); __syncthreads();
    #pragma unroll 1
    for (int cn = 0; cn < 8; cn++) {
        const int b = cn & 1;
        if (cn < 7) { cpW2(cn + 1, b ^ 1); cp_commit(); }

        float accB[2][8][4];
        #pragma unroll
        for (int mb = 0; mb < 2; mb++)
            #pragma unroll
            for (int nb = 0; nb < 8; nb++)
                #pragma unroll
                for (int q = 0; q < 4; q++) accB[mb][nb][q] = 0.f;

        uint32_t Wb = SP + b * 34816;
        #pragma unroll
        for (int ks = 0; ks < 4; ks++) {
            uint32_t ah[2][4], al[2][4];
            #pragma unroll
            for (int mb = 0; mb < 2; mb++) {
                uint32_t ad = SB + (wm*32 + mb*16 + (lid & 15)) * 144
                            + ks * 32 + ((lid >> 4) << 4);
                ldsm4(ad, ah[mb]);
                ldsm4(ad + 18432, al[mb]);
            }
            #pragma unroll
            for (int j = 0; j < 4; j++) {
                uint32_t bd = Wb + (ks*16 + (lid & 15)) * 272
                            + (wn*64 + j*16 + ((lid >> 4) << 3)) * 2;
                uint32_t bh[4], bl[4];
                ldsm4t(bd, bh);
                ldsm4t(bd + 17408, bl);
                #pragma unroll
                for (int mb = 0; mb < 2; mb++)
                    #pragma unroll
                    for (int nn = 0; nn < 2; nn++) {
                        int nb = j*2 + nn;
                        mma16816(accB[mb][nb], ah[mb], bh + nn*2);
                        mma16816(accB[mb][nb], ah[mb], bl + nn*2);
                        mma16816(accB[mb][nb], al[mb], bh + nn*2);
                    }
            }
        }

        // epilogue: + b2, * gate weight, atomic-add into out (exactly 2 adds/element,
        // fp add of two values is commutative -> bitwise deterministic)
        #pragma unroll
        for (int mb = 0; mb < 2; mb++) {
            int r  = wm*32 + mb*16 + (lid >> 2);
            int d0 = s_dst[r],     d1 = s_dst[r + 8];
            float w0 = s_w[r],     w1 = s_w[r + 8];
            #pragma unroll
            for (int nb = 0; nb < 8; nb++) {
                int col = cn*128 + wn*64 + nb*8 + (lid & 3) * 2;
                float bb0 = b2[e * D_OUT + col], bb1 = b2[e * D_OUT + col + 1];
                if (d0 >= 0)
                    red2(&out[(size_t)(d0 >> 1) * D_OUT + col],
                         w0 * (accB[mb][nb][0] + bb0), w0 * (accB[mb][nb][1] + bb1));
                if (d1 >= 0)
                    red2(&out[(size_t)(d1 >> 1) * D_OUT + col],
                         w1 * (accB[mb][nb][2] + bb0), w1 * (accB[mb][nb][3] + bb1));
            }
        }
        if (cn < 7) { cp_wait<0>(); __syncthreads(); }
    }
}

// ---------------- launch ----------------
extern "C" void kernel_launch(void* const* d_in, const int* in_sizes, int n_in,
                              void* d_out, int out_size) {
    const float* x  = (const float*)d_in[0];
    const float* Wg = (const float*)d_in[1];
    const float* bg = (const float*)d_in[2];
    const float* W1 = (const float*)d_in[3];
    const float* b1 = (const float*)d_in[4];
    const float* W2 = (const float*)d_in[5];
    const float* b2 = (const float*)d_in[6];
    float* out = (float*)d_out;

    cudaFuncSetAttribute(expert_kernel,
                         cudaFuncAttributeMaxDynamicSharedMemorySize, SM_DYN);

    __nv_bfloat16 *w1hi, *w1lo, *w2hi, *w2lo;
    cudaGetSymbolAddress((void**)&w1hi, g_W1s_hi);
    cudaGetSymbolAddress((void**)&w1lo, g_W1s_lo);
    cudaGetSymbolAddress((void**)&w2hi, g_W2s_hi);
    cudaGetSymbolAddress((void**)&w2lo, g_W2s_lo);

    reset_kernel<<<1, 32>>>();
    zero_out_kernel<<<(B_TOK * D_OUT / 4) / 256, 256>>>((float4*)out);
    const int NW = NE * D_IN * NH;
    split_kernel<<<(NW + 255) / 256, 256>>>(W1, w1hi, w1lo, NW);
    split_kernel<<<(NW + 255) / 256, 256>>>(W2, w2hi, w2lo, NW);
    gate_kernel<<<B_TOK / GT, 128>>>(x, Wg, bg);
    expert_kernel<<<dim3(B_TOK / TILE_M, NE), 256, SM_DYN>>>(x, b1, b2, out);
}

// round 11
// speedup vs baseline: 1.0412x; 1.0412x over previous
#include <cuda_runtime.h>
#include <cuda_bf16.h>
#include <cstdint>

#define B_TOK 8192
#define D_IN  1024
#define D_OUT 1024
#define NE    16
#define TOPK  2
#define NH    64
#define TILE_M 128

// ---------------- device scratch (static allocations only) ----------------
__device__ int   g_cnt[NE];
__device__ int   g_dst[NE * B_TOK];
__device__ float g_gw[NE * B_TOK];

// bf16 hi/lo split weights (same layout as source, no transpose)
__device__ __nv_bfloat16 g_W1s_hi[NE * D_IN * NH];    // [e][k][h]
__device__ __nv_bfloat16 g_W1s_lo[NE * D_IN * NH];
__device__ __nv_bfloat16 g_W2s_hi[NE * NH * D_OUT];   // [e][h][o]
__device__ __nv_bfloat16 g_W2s_lo[NE * NH * D_OUT];

// ---------------- helpers ----------------
__device__ __forceinline__ uint32_t smem_u32(const void* p) {
    uint32_t a;
    asm("{ .reg .u64 t; cvta.to.shared.u64 t, %1; cvt.u32.u64 %0, t; }" : "=r"(a) : "l"(p));
    return a;
}
__device__ __forceinline__ void cp16s(uint32_t sa, const void* g) {
    asm volatile("cp.async.cg.shared.global [%0], [%1], 16;\n" :: "r"(sa), "l"(g));
}
__device__ __forceinline__ void cp_commit() { asm volatile("cp.async.commit_group;\n"); }
template<int N> __device__ __forceinline__ void cp_wait() {
    asm volatile("cp.async.wait_group %0;\n" :: "n"(N));
}
__device__ __forceinline__ void sts128(uint32_t a, uint32_t r0, uint32_t r1,
                                       uint32_t r2, uint32_t r3) {
    asm volatile("st.shared.v4.b32 [%0], {%1,%2,%3,%4};"
                 :: "r"(a), "r"(r0), "r"(r1), "r"(r2), "r"(r3) : "memory");
}
__device__ __forceinline__ void ldsm4(uint32_t a, uint32_t* r) {
    asm volatile("ldmatrix.sync.aligned.m8n8.x4.shared.b16 {%0,%1,%2,%3}, [%4];"
                 : "=r"(r[0]), "=r"(r[1]), "=r"(r[2]), "=r"(r[3]) : "r"(a));
}
__device__ __forceinline__ void ldsm4t(uint32_t a, uint32_t* r) {
    asm volatile("ldmatrix.sync.aligned.m8n8.x4.trans.shared.b16 {%0,%1,%2,%3}, [%4];"
                 : "=r"(r[0]), "=r"(r[1]), "=r"(r[2]), "=r"(r[3]) : "r"(a));
}
__device__ __forceinline__ void mma16816(float* d, const uint32_t* a, const uint32_t* b) {
    asm volatile("mma.sync.aligned.m16n8k16.row.col.f32.bf16.bf16.f32 "
                 "{%0,%1,%2,%3}, {%4,%5,%6,%7}, {%8,%9}, {%0,%1,%2,%3};"
                 : "+f"(d[0]), "+f"(d[1]), "+f"(d[2]), "+f"(d[3])
                 : "r"(a[0]), "r"(a[1]), "r"(a[2]), "r"(a[3]), "r"(b[0]), "r"(b[1]));
}
__device__ __forceinline__ void red2(float* gaddr, float v0, float v1) {
    asm volatile("red.global.add.v2.f32 [%0], {%1, %2};"
                 :: "l"(gaddr), "f"(v0), "f"(v1) : "memory");
}

// pack (lo half = f0, hi half = f1) into bf16x2
__device__ __forceinline__ uint32_t pk_bf(float f0, float f1) {
    uint32_t r;
    asm("cvt.rn.bf16x2.f32 %0, %1, %2;" : "=r"(r) : "f"(f1), "f"(f0));
    return r;
}
__device__ __forceinline__ float bf_lo_f(uint32_t p) { return __uint_as_float(p << 16); }
__device__ __forceinline__ float bf_hi_f(uint32_t p) { return __uint_as_float(p & 0xFFFF0000u); }

__device__ __forceinline__ void top2_insert(float v, int e, float& v0, int& i0,
                                            float& v1, int& i1) {
    if (v > v0 || (v == v0 && e < i0)) { v1 = v0; i1 = i0; v0 = v; i0 = e; }
    else if (v > v1 || (v == v1 && e < i1)) { v1 = v; i1 = e; }
}

// ---------------- kernel 0: reset counters (must precede gate atomics) ----------------
__global__ void reset_kernel() {
    if (threadIdx.x < NE) g_cnt[threadIdx.x] = 0;
}

// ---------------- kernel 1: fused prep (gate | split W1 | split W2 | zero out) ----------
// 128 threads/block. Role by blockIdx.x:
//   [0,256)      gate (validated math, bitwise unchanged)
//   [256,384)    split W1  (16 float4/thread)
//   [384,512)    split W2
//   [512,1024)   zero out  (32 float4/thread)
#define GT 32
#define GATE_BLKS  256
#define SPLIT_BLKS 128
#define ZERO_BLKS  512
#define PREP_BLKS  (GATE_BLKS + 2 * SPLIT_BLKS + ZERO_BLKS)

__device__ __forceinline__ void split_role(const float* __restrict__ src,
                                           __nv_bfloat16* __restrict__ dhi,
                                           __nv_bfloat16* __restrict__ dlo,
                                           int blk, int tid) {
    // NE*D_IN*NH floats = 262144 float4; 128 blocks * 128 thr * 16 f4
    const float4* s4 = (const float4*)src;
    uint2* h2 = (uint2*)dhi;
    uint2* l2 = (uint2*)dlo;
    int base = blk * 2048;
    #pragma unroll 4
    for (int i = 0; i < 16; i++) {
        int f = base + i * 128 + tid;
        float4 v = s4[f];
        uint32_t h0 = pk_bf(v.x, v.y), h1 = pk_bf(v.z, v.w);
        uint2 hh = make_uint2(h0, h1);
        uint2 ll = make_uint2(pk_bf(v.x - bf_lo_f(h0), v.y - bf_hi_f(h0)),
                              pk_bf(v.z - bf_lo_f(h1), v.w - bf_hi_f(h1)));
        h2[f] = hh;
        l2[f] = ll;
    }
}

__global__ void __launch_bounds__(128) prep_kernel(
    const float* __restrict__ x,  const float* __restrict__ Wg,
    const float* __restrict__ bg, const float* __restrict__ W1,
    const float* __restrict__ W2, float* __restrict__ out)
{
    const int bid = blockIdx.x;
    const int tid = threadIdx.x;

    if (bid >= GATE_BLKS) {
        if (bid < GATE_BLKS + SPLIT_BLKS) {
            split_role(W1, g_W1s_hi, g_W1s_lo, bid - GATE_BLKS, tid);
        } else if (bid < GATE_BLKS + 2 * SPLIT_BLKS) {
            split_role(W2, g_W2s_hi, g_W2s_lo, bid - GATE_BLKS - SPLIT_BLKS, tid);
        } else {
            // zero: 2097152 float4 over 512 blocks = 4096/block = 32/thread
            float4* o4 = (float4*)out;
            int base = (bid - GATE_BLKS - 2 * SPLIT_BLKS) * 4096;
            float4 z = make_float4(0.f, 0.f, 0.f, 0.f);
            #pragma unroll 8
            for (int i = 0; i < 32; i++) o4[base + i * 128 + tid] = z;
        }
        return;
    }

    // ---------------- gate role (validated; math bitwise unchanged) ----------------
    __shared__ float Xs[4][GT][68];
    __shared__ float Wgs[4][64][16];
    const int tl = tid >> 2;           // token-in-block 0..31
    const int eb = tid & 3;            // expert quad 0..3
    const int t0 = bid * GT;

    const uint32_t xs_b  = smem_u32(&Xs[0][0][0]);
    const uint32_t wgs_b = smem_u32(&Wgs[0][0][0]);

    auto loadX = [&](int c, int b) {
        #pragma unroll
        for (int i = 0; i < 4; i++) {
            int f = tid + i * 128;          // 512 float4 tasks
            int r = f >> 4, c4 = f & 15;
            cp16s(xs_b + (uint32_t)(b * GT * 68 + r * 68 + c4 * 4) * 4,
                  &x[(t0 + r) * D_IN + c * 64 + c4 * 4]);
        }
    };
    auto loadW = [&](int c, int b) {
        #pragma unroll
        for (int i = 0; i < 2; i++) {
            int f = tid + i * 128;          // 256 float4 tasks
            int r = f >> 2, c4 = f & 3;
            cp16s(wgs_b + (uint32_t)(b * 64 * 16 + r * 16 + c4 * 4) * 4,
                  &Wg[(c * 64 + r) * NE + c4 * 4]);
        }
    };

    float tot0 = 0.f, tot1 = 0.f, tot2 = 0.f, tot3 = 0.f;

    #pragma unroll
    for (int s = 0; s < 3; s++) { loadX(s, s); loadW(s, s); cp_commit(); }

    #pragma unroll 1
    for (int c = 0; c < 16; c++) {
        const int b = c & 3;
        cp_wait<2>(); __syncthreads();
        if (c + 3 < 16) { loadX(c + 3, (c + 3) & 3); loadW(c + 3, (c + 3) & 3); }
        cp_commit();
        float a0 = 0.f, a1 = 0.f, a2 = 0.f, a3 = 0.f;
        #pragma unroll 16
        for (int kk = 0; kk < 64; kk++) {
            float xv = Xs[b][tl][kk];
            float4 w = *(const float4*)&Wgs[b][kk][eb * 4];
            a0 += xv * w.x; a1 += xv * w.y; a2 += xv * w.z; a3 += xv * w.w;
        }
        tot0 += a0; tot1 += a1; tot2 += a2; tot3 += a3;
    }

    float4 bgv = *(const float4*)&bg[eb * 4];
    tot0 += bgv.x; tot1 += bgv.y; tot2 += bgv.z; tot3 += bgv.w;

    float v0 = -3.402823466e38f, v1 = -3.402823466e38f;
    int   i0 = NE, i1 = NE;
    top2_insert(tot0, eb * 4 + 0, v0, i0, v1, i1);
    top2_insert(tot1, eb * 4 + 1, v0, i0, v1, i1);
    top2_insert(tot2, eb * 4 + 2, v0, i0, v1, i1);
    top2_insert(tot3, eb * 4 + 3, v0, i0, v1, i1);

    const unsigned m = 0xFFFFFFFFu;
    #pragma unroll
    for (int d = 1; d < 4; d <<= 1) {
        float ov0 = __shfl_xor_sync(m, v0, d);
        int   oi0 = __shfl_xor_sync(m, i0, d);
        float ov1 = __shfl_xor_sync(m, v1, d);
        int   oi1 = __shfl_xor_sync(m, i1, d);
        top2_insert(ov0, oi0, v0, i0, v1, i1);
        top2_insert(ov1, oi1, v0, i0, v1, i1);
    }

    if (eb == 0) {
        int tok = t0 + tl;
        float r   = expf(v1 - v0);
        float inv = 1.0f / (1.0f + r);
        int p0 = atomicAdd(&g_cnt[i0], 1);
        g_dst[i0 * B_TOK + p0] = tok * 2;
        g_gw [i0 * B_TOK + p0] = inv;
        int p1 = atomicAdd(&g_cnt[i1], 1);
        g_dst[i1 * B_TOK + p1] = tok * 2 + 1;
        g_gw [i1 * B_TOK + p1] = r * inv;
    }
}

// ---------------- kernel 2: HMMA grouped expert MLP (unchanged, validated) ----------------
// dyn smem (from 1024-aligned base SB), all byte offsets:
//   Hhi @ 0 (18432 = 128 rows * 144B)   Hlo @ 18432          (36864 total)
//   pool @ 36864:
//     Phase A buf b @ pool + b*55296:
//       Xhi(18432: 128r x 144B) Xlo(+18432) W1hi(+36864, 64r x 144B = 9216) W1lo(+46080)
//     Phase B buf b @ pool + b*34816:
//       W2hi(17408: 64r x 272B) W2lo(+17408)
#define SM_POOL 36864
#define SM_DYN  (36864 + 2*55296 + 1024)

__global__ void __launch_bounds__(256, 1) expert_kernel(
    const float* __restrict__ x, const float* __restrict__ b1,
    const float* __restrict__ b2, float* __restrict__ out)
{
    const int e    = blockIdx.y;
    const int n    = g_cnt[e];
    const int base = blockIdx.x * TILE_M;
    if (base >= n) return;

    const int tid = threadIdx.x;
    const int wid = tid >> 5, lid = tid & 31;
    const int wm  = wid & 3, wn = wid >> 2;     // warp grid 4(M) x 2(N)

    __shared__ int   s_dst[TILE_M];
    __shared__ int   s_tok[TILE_M];
    __shared__ float s_w[TILE_M];
    extern __shared__ char dynsm[];
    const uint32_t SB = (smem_u32(dynsm) + 1023u) & ~1023u;
    const uint32_t SP = SB + SM_POOL;

    if (tid < TILE_M) {
        int slot = base + tid;
        if (slot < n) {
            int d = g_dst[e * B_TOK + slot];
            s_dst[tid] = d; s_tok[tid] = d >> 1;
            s_w[tid] = g_gw[e * B_TOK + slot];
        } else { s_dst[tid] = -1; s_tok[tid] = 0; s_w[tid] = 0.f; }
    }
    __syncthreads();

    // ================= Phase A: H = relu(X @ W1 + b1) =================
    const int arow = tid >> 1, ahalf = tid & 1;
    const float* xrow = x + (size_t)s_tok[arow] * D_IN + ahalf * 32;
    float4 xr[8];

    auto ldgX = [&](int c) {
        const float* p = xrow + c * 64;
        #pragma unroll
        for (int j = 0; j < 8; j++) xr[j] = *(const float4*)(p + j * 4);
    };
    auto stsX = [&](int b) {
        uint32_t hib = SP + b * 55296;
        uint32_t lob = hib + 18432;
        uint32_t hi[16], lo[16];
        #pragma unroll
        for (int j = 0; j < 8; j++) {
            float f0 = xr[j].x, f1 = xr[j].y, f2 = xr[j].z, f3 = xr[j].w;
            uint32_t h0 = pk_bf(f0, f1), h1 = pk_bf(f2, f3);
            hi[2*j] = h0; hi[2*j+1] = h1;
            lo[2*j]   = pk_bf(f0 - bf_lo_f(h0), f1 - bf_hi_f(h0));
            lo[2*j+1] = pk_bf(f2 - bf_lo_f(h1), f3 - bf_hi_f(h1));
        }
        uint32_t rb = arow * 144 + ahalf * 64;
        #pragma unroll
        for (int q = 0; q < 4; q++) {
            sts128(hib + rb + q * 16, hi[4*q], hi[4*q+1], hi[4*q+2], hi[4*q+3]);
            sts128(lob + rb + q * 16, lo[4*q], lo[4*q+1], lo[4*q+2], lo[4*q+3]);
        }
    };
    auto cpW1 = [&](int c, int b) {
        uint32_t hib = SP + b * 55296 + 36864;
        uint32_t lob = hib + 9216;
        #pragma unroll
        for (int i = 0; i < 2; i++) {
            int f = tid + i * 256;               // 0..511
            int r = f >> 3, s = f & 7;
            uint32_t off = r * 144 + s * 16;
            int gi = (e * D_IN + c * 64 + r) * NH + s * 8;
            cp16s(hib + off, &g_W1s_hi[gi]);
            cp16s(lob + off, &g_W1s_lo[gi]);
        }
    };

    float accA[2][4][4];
    #pragma unroll
    for (int mb = 0; mb < 2; mb++)
        #pragma unroll
        for (int nb = 0; nb < 4; nb++)
            #pragma unroll
            for (int q = 0; q < 4; q++) accA[mb][nb][q] = 0.f;

    auto computeA = [&](int b) {
        uint32_t Xb = SP + b * 55296;
        uint32_t Wb = Xb + 36864;
        #pragma unroll
        for (int ks = 0; ks < 4; ks++) {
            uint32_t ah[2][4], al[2][4];
            #pragma unroll
            for (int mb = 0; mb < 2; mb++) {
                uint32_t ad = Xb + (wm*32 + mb*16 + (lid & 15)) * 144
                            + ks * 32 + ((lid >> 4) << 4);
                ldsm4(ad, ah[mb]);
                ldsm4(ad + 18432, al[mb]);
            }
            #pragma unroll
            for (int j = 0; j < 2; j++) {
                uint32_t bd = Wb + (ks*16 + (lid & 15)) * 144
                            + (wn*32 + j*16 + ((lid >> 4) << 3)) * 2;
                uint32_t bh[4], bl[4];
                ldsm4t(bd, bh);
                ldsm4t(bd + 9216, bl);
                #pragma unroll
                for (int mb = 0; mb < 2; mb++)
                    #pragma unroll
                    for (int nn = 0; nn < 2; nn++) {
                        int nb = j*2 + nn;
                        mma16816(accA[mb][nb], ah[mb], bh + nn*2);
                        mma16816(accA[mb][nb], ah[mb], bl + nn*2);
                        mma16816(accA[mb][nb], al[mb], bh + nn*2);
                    }
            }
        }
    };

    ldgX(0);
    stsX(0);
    cpW1(0, 0); cp_commit();
    ldgX(1);
    cp_wait<0>(); __syncthreads();
    #pragma unroll 1
    for (int c = 0; c < 16; c++) {
        const int b = c & 1;
        if (c < 15) {
            stsX(b ^ 1);                      // xr holds chunk c+1
            cpW1(c + 1, b ^ 1); cp_commit();
            if (c < 14) ldgX(c + 2);
        }
        computeA(b);
        if (c < 15) { cp_wait<0>(); __syncthreads(); }
    }

    // ---- epilogue A: bias + relu -> bf16 hi/lo H tiles ----
    {
        char* SBp = dynsm + (SB - smem_u32(dynsm));
        #pragma unroll
        for (int mb = 0; mb < 2; mb++) {
            int r = wm*32 + mb*16 + (lid >> 2);
            #pragma unroll
            for (int nb = 0; nb < 4; nb++) {
                int col = wn*32 + nb*8 + (lid & 3) * 2;
                float bb0 = b1[e * NH + col], bb1 = b1[e * NH + col + 1];
                float v0 = fmaxf(accA[mb][nb][0] + bb0, 0.f);
                float v1 = fmaxf(accA[mb][nb][1] + bb1, 0.f);
                uint32_t h = pk_bf(v0, v1);
                uint32_t l = pk_bf(v0 - bf_lo_f(h), v1 - bf_hi_f(h));
                *(uint32_t*)(SBp + r * 144 + col * 2)         = h;
                *(uint32_t*)(SBp + 18432 + r * 144 + col * 2) = l;
                v0 = fmaxf(accA[mb][nb][2] + bb0, 0.f);
                v1 = fmaxf(accA[mb][nb][3] + bb1, 0.f);
                h = pk_bf(v0, v1);
                l = pk_bf(v0 - bf_lo_f(h), v1 - bf_hi_f(h));
                *(uint32_t*)(SBp + (r + 8) * 144 + col * 2)         = h;
                *(uint32_t*)(SBp + 18432 + (r + 8) * 144 + col * 2) = l;
            }
        }
    }
    __syncthreads();

    // ================= Phase B: Y = w * (H @ W2 + b2) -> red.add to out =================
    auto cpW2 = [&](int cn, int b) {
        uint32_t hib = SP + b * 34816;
        uint32_t lob = hib + 17408;
        #pragma unroll
        for (int i = 0; i < 4; i++) {
            int f = tid + i * 256;               // 0..1023
            int r = f >> 4, s = f & 15;
            uint32_t off = r * 272 + s * 16;
            int gi = (e * NH + r) * D_OUT + cn * 128 + s * 8;
            cp16s(hib + off, &g_W2s_hi[gi]);
            cp16s(lob + off, &g_W2s_lo[gi]);
        }
    };

    cpW2(0, 0); cp_commit();
    cp_wait<0>(); __syncthreads();
    #pragma unroll 1
    for (int cn = 0; cn < 8; cn++) {
        const int b = cn & 1;
        if (cn < 7) { cpW2(cn + 1, b ^ 1); cp_commit(); }

        float accB[2][8][4];
        #pragma unroll
        for (int mb = 0; mb < 2; mb++)
            #pragma unroll
            for (int nb = 0; nb < 8; nb++)
                #pragma unroll
                for (int q = 0; q < 4; q++) accB[mb][nb][q] = 0.f;

        uint32_t Wb = SP + b * 34816;
        #pragma unroll
        for (int ks = 0; ks < 4; ks++) {
            uint32_t ah[2][4], al[2][4];
            #pragma unroll
            for (int mb = 0; mb < 2; mb++) {
                uint32_t ad = SB + (wm*32 + mb*16 + (lid & 15)) * 144
                            + ks * 32 + ((lid >> 4) << 4);
                ldsm4(ad, ah[mb]);
                ldsm4(ad + 18432, al[mb]);
            }
            #pragma unroll
            for (int j = 0; j < 4; j++) {
                uint32_t bd = Wb + (ks*16 + (lid & 15)) * 272
                            + (wn*64 + j*16 + ((lid >> 4) << 3)) * 2;
                uint32_t bh[4], bl[4];
                ldsm4t(bd, bh);
                ldsm4t(bd + 17408, bl);
                #pragma unroll
                for (int mb = 0; mb < 2; mb++)
                    #pragma unroll
                    for (int nn = 0; nn < 2; nn++) {
                        int nb = j*2 + nn;
                        mma16816(accB[mb][nb], ah[mb], bh + nn*2);
                        mma16816(accB[mb][nb], ah[mb], bl + nn*2);
                        mma16816(accB[mb][nb], al[mb], bh + nn*2);
                    }
            }
        }

        // epilogue: + b2, * gate weight, atomic-add into out (exactly 2 adds/element,
        // fp add of two values is commutative -> bitwise deterministic)
        #pragma unroll
        for (int mb = 0; mb < 2; mb++) {
            int r  = wm*32 + mb*16 + (lid >> 2);
            int d0 = s_dst[r],     d1 = s_dst[r + 8];
            float w0 = s_w[r],     w1 = s_w[r + 8];
            #pragma unroll
            for (int nb = 0; nb < 8; nb++) {
                int col = cn*128 + wn*64 + nb*8 + (lid & 3) * 2;
                float bb0 = b2[e * D_OUT + col], bb1 = b2[e * D_OUT + col + 1];
                if (d0 >= 0)
                    red2(&out[(size_t)(d0 >> 1) * D_OUT + col],
                         w0 * (accB[mb][nb][0] + bb0), w0 * (accB[mb][nb][1] + bb1));
                if (d1 >= 0)
                    red2(&out[(size_t)(d1 >> 1) * D_OUT + col],
                         w1 * (accB[mb][nb][2] + bb0), w1 * (accB[mb][nb][3] + bb1));
            }
        }
        if (cn < 7) { cp_wait<0>(); __syncthreads(); }
    }
}

// ---------------- launch ----------------
extern "C" void kernel_launch(void* const* d_in, const int* in_sizes, int n_in,
                              void* d_out, int out_size) {
    const float* x  = (const float*)d_in[0];
    const float* Wg = (const float*)d_in[1];
    const float* bg = (const float*)d_in[2];
    const float* W1 = (const float*)d_in[3];
    const float* b1 = (const float*)d_in[4];
    const float* W2 = (const float*)d_in[5];
    const float* b2 = (const float*)d_in[6];
    float* out = (float*)d_out;

    cudaFuncSetAttribute(expert_kernel,
                         cudaFuncAttributeMaxDynamicSharedMemorySize, SM_DYN);

    reset_kernel<<<1, 32>>>();
    prep_kernel<<<PREP_BLKS, 128>>>(x, Wg, bg, W1, W2, out);
    expert_kernel<<<dim3(B_TOK / TILE_M, NE), 256, SM_DYN>>>(x, b1, b2, out);
}